// round 3
// baseline (speedup 1.0000x reference)
#include <cuda_runtime.h>
#include <cuda_bf16.h>

// ---------------------------------------------------------------------------
// GRU with reset-on-terminate, T=8192, D_IN=H=1024.
// Segment-parallel formulation: every termination resets h to 0 (and
// last_state is the initial carry), so positions bucketed by "local step
// index" l[t] = t - last_reset(t) form batched GEMMs. Serial depth = max
// segment length (~20 for p=0.5 terminations) instead of 8192.
//
// R2 fix: terminations arrive as int32 (harness converts bool -> int32;
// only float32/int32/bf16 exist in the contract). Was read as uint8 -> ~half
// the positions got wrong segment ids -> rel_err 0.4977.
// ---------------------------------------------------------------------------

#define T_STEPS 8192
#define HDIM    1024
#define N3H     3072
#define NT      256      // threads per block
#define GRID_BLOCKS 296  // <= 2 * 148 SMs, co-resident via launch_bounds(256,2)

// ---- persistent device scratch (no dynamic allocation allowed) ----
__device__ float g_gi[(size_t)T_STEPS * N3H];   // input-side preactivations
__device__ float g_gh[(size_t)T_STEPS * N3H];   // recurrent preactivations (per step, bucket-packed)
__device__ int   g_perm[T_STEPS];               // positions sorted by local step
__device__ int   g_cnt[T_STEPS];                // histogram / scatter cursors
__device__ int   g_off[T_STEPS + 1];            // bucket offsets
__device__ int   g_l[T_STEPS];                  // local step index per position
__device__ int   g_maxL;
__device__ unsigned long long g_bar;            // monotonic grid barrier counter

// ---------------------------------------------------------------------------
// Grid-wide barrier: monotonic counter, no reset (race-free across phases and
// across graph replays; every launch performs an identical barrier count).
// ---------------------------------------------------------------------------
__device__ __forceinline__ void grid_sync() {
    __syncthreads();
    if (threadIdx.x == 0) {
        __threadfence();
        unsigned long long my = atomicAdd(&g_bar, 1ULL) + 1ULL;
        unsigned long long target = ((my + GRID_BLOCKS - 1ULL) / GRID_BLOCKS) * GRID_BLOCKS;
        while (atomicAdd(&g_bar, 0ULL) < target) { __nanosleep(256); }
        __threadfence();
    }
    __syncthreads();
}

// ---------------------------------------------------------------------------
// Bucketize positions by local step index (block 0 only, 256 threads).
// term is int32 (0/1).
// ---------------------------------------------------------------------------
__device__ void bucketize(const int* __restrict__ term) {
    __shared__ int s_cm[NT];
    __shared__ int s_ml[NT];
    const int tid = threadIdx.x;

    for (int i = tid; i < T_STEPS; i += NT) g_cnt[i] = 0;
    __syncthreads();

    const int t0 = tid * 32;  // 256 * 32 = 8192
    // pass 1: per-chunk max reset position
    int cm = -1;
#pragma unroll
    for (int i = 0; i < 32; i++) if (term[t0 + i] != 0) cm = t0 + i;
    s_cm[tid] = cm;
    __syncthreads();
    // exclusive max over preceding chunks (O(256) per thread, fine)
    int pre = -1;
    for (int c = 0; c < tid; c++) pre = max(pre, s_cm[c]);
    // pass 2: local indices + histogram
    int run = pre, ml = 0;
    for (int i = 0; i < 32; i++) {
        int t = t0 + i;
        if (term[t] != 0) run = t;
        int l = (run < 0) ? t : (t - run);
        g_l[t] = l;
        atomicAdd(&g_cnt[l], 1);
        ml = max(ml, l);
    }
    s_ml[tid] = ml;
    __syncthreads();

    if (tid == 0) {
        int m = 0;
        for (int c = 0; c < NT; c++) m = max(m, s_ml[c]);
        g_maxL = m;
        int o = 0;
        for (int s = 0; s <= m; s++) { g_off[s] = o; o += g_cnt[s]; }
        g_off[m + 1] = o;   // == T_STEPS
        for (int s = 0; s <= m; s++) g_cnt[s] = 0;  // reuse as scatter cursors
    }
    __syncthreads();

    for (int i = 0; i < 32; i++) {
        int t = t0 + i;
        int l = g_l[t];
        int pos = g_off[l] + atomicAdd(&g_cnt[l], 1);
        g_perm[pos] = t;
    }
    // visibility to other blocks established by the following grid_sync
}

// ---------------------------------------------------------------------------
// Tiled fp32 GEMM: C[M,3072] = A[M,1024] @ B[1024,3072] (+bias).
// BM=64, BN=64, BK=16, 256 threads, 4x4 microtile.
// phase2: A rows gathered via g_perm (h_{t-1} rows of the output buffer).
// ---------------------------------------------------------------------------
__device__ void do_gemm(const float* __restrict__ A_base,
                        const float* __restrict__ Bmat,
                        float* __restrict__ C,
                        const float* __restrict__ bias,  // nullptr for phase2
                        int M, int phase2, int off_s) {
    __shared__ float As[16][64];
    __shared__ float Bs[16][64];

    const int tid = threadIdx.x;
    const int tx4 = (tid & 15) * 4;
    const int ty4 = (tid >> 4) * 4;
    const int ar  = tid >> 2;          // A load row within tile (0..63)
    const int akv = (tid & 3) * 4;     // A load k offset (0,4,8,12)
    const int br  = tid >> 4;          // B load k row (0..15)
    const int bnc = (tid & 15) * 4;    // B load col offset

    const int tilesM = (M + 63) >> 6;
    const int numTiles = tilesM * 48;  // 3072/64 = 48 col tiles

    for (int tile = blockIdx.x; tile < numTiles; tile += GRID_BLOCKS) {
        const int tm = tile / 48;
        const int tn = tile - tm * 48;
        const int nbase = tn * 64;

        const int gm = tm * 64 + ar;
        const float* ap = nullptr;
        if (gm < M) {
            if (!phase2) {
                ap = A_base + (size_t)gm * HDIM;
            } else {
                int t = __ldcg(&g_perm[off_s + gm]);  // t >= 1 in all s>=1 buckets
                ap = A_base + (size_t)(t - 1) * HDIM;
            }
        }

        float acc[4][4] = {};

        for (int kb = 0; kb < HDIM; kb += 16) {
            float4 av4 = make_float4(0.f, 0.f, 0.f, 0.f);
            if (ap) {
                const float4* p = (const float4*)(ap + kb + akv);
                av4 = phase2 ? __ldcg(p) : *p;
            }
            As[akv + 0][ar] = av4.x;
            As[akv + 1][ar] = av4.y;
            As[akv + 2][ar] = av4.z;
            As[akv + 3][ar] = av4.w;

            *(float4*)&Bs[br][bnc] =
                *(const float4*)(Bmat + (size_t)(kb + br) * N3H + nbase + bnc);

            __syncthreads();
#pragma unroll
            for (int k = 0; k < 16; k++) {
                float4 av = *(float4*)&As[k][ty4];
                float4 bv = *(float4*)&Bs[k][tx4];
                acc[0][0] += av.x * bv.x; acc[0][1] += av.x * bv.y;
                acc[0][2] += av.x * bv.z; acc[0][3] += av.x * bv.w;
                acc[1][0] += av.y * bv.x; acc[1][1] += av.y * bv.y;
                acc[1][2] += av.y * bv.z; acc[1][3] += av.y * bv.w;
                acc[2][0] += av.z * bv.x; acc[2][1] += av.z * bv.y;
                acc[2][2] += av.z * bv.z; acc[2][3] += av.z * bv.w;
                acc[3][0] += av.w * bv.x; acc[3][1] += av.w * bv.y;
                acc[3][2] += av.w * bv.z; acc[3][3] += av.w * bv.w;
            }
            __syncthreads();
        }

#pragma unroll
        for (int i = 0; i < 4; i++) {
            int rowg = tm * 64 + ty4 + i;
            if (rowg < M) {
                float4 o;
                o.x = acc[i][0]; o.y = acc[i][1]; o.z = acc[i][2]; o.w = acc[i][3];
                if (bias) {
                    o.x += bias[nbase + tx4 + 0];
                    o.y += bias[nbase + tx4 + 1];
                    o.z += bias[nbase + tx4 + 2];
                    o.w += bias[nbase + tx4 + 3];
                }
                *(float4*)&C[(size_t)rowg * N3H + nbase + tx4] = o;
            }
        }
    }
}

// ---------------------------------------------------------------------------
// Fused gate pass for bucket s.
// ---------------------------------------------------------------------------
__device__ void gates_pass(int s, int off, int cnt,
                           const float* __restrict__ last_state,
                           const float* __restrict__ Wh,
                           const float* __restrict__ bhn,
                           const int* __restrict__ term,
                           float* __restrict__ out) {
    const long total = (long)cnt * HDIM;
    const bool term0 = (term[0] != 0);
    for (long idx = (long)blockIdx.x * NT + threadIdx.x; idx < total;
         idx += (long)GRID_BLOCKS * NT) {
        int r = (int)(idx >> 10);
        int j = (int)(idx & 1023);
        int t = __ldcg(&g_perm[off + r]);
        size_t gb = (size_t)t * N3H;
        float gi_r = __ldcg(&g_gi[gb + j]);
        float gi_z = __ldcg(&g_gi[gb + HDIM + j]);
        float gi_n = __ldcg(&g_gi[gb + 2 * HDIM + j]);

        float gh_r = 0.f, gh_z = 0.f, gh_n = 0.f, hold = 0.f;
        if (s > 0) {
            hold = __ldcg(&out[(size_t)(t - 1) * HDIM + j]);
            size_t hb = (size_t)r * N3H;
            gh_r = __ldcg(&g_gh[hb + j]);
            gh_z = __ldcg(&g_gh[hb + HDIM + j]);
            gh_n = __ldcg(&g_gh[hb + 2 * HDIM + j]);
        } else if (t == 0 && !term0) {
            // only position whose carry is last_state (general-case safety;
            // in the given data last_state == 0)
            for (int k = 0; k < HDIM; k++) {
                float hv = last_state[k];
                const float* wr = Wh + (size_t)k * N3H + j;
                gh_r += hv * wr[0];
                gh_z += hv * wr[HDIM];
                gh_n += hv * wr[2 * HDIM];
            }
            hold = last_state[j];
        }

        float rg = 1.f / (1.f + expf(-(gi_r + gh_r)));
        float zg = 1.f / (1.f + expf(-(gi_z + gh_z)));
        float ng = tanhf(gi_n + rg * (gh_n + bhn[j]));
        float h  = (1.f - zg) * ng + zg * hold;

        out[(size_t)t * HDIM + j] = h;                              // y_t
        out[(size_t)T_STEPS * HDIM + (size_t)t * HDIM + j] = h;     // new_states
    }
}

// ---------------------------------------------------------------------------
// Persistent kernel.
// ---------------------------------------------------------------------------
__global__ __launch_bounds__(NT, 2)
void gru_persistent(const float* __restrict__ inputs,
                    const int* __restrict__ term,
                    const float* __restrict__ last_state,
                    const float* __restrict__ Wi,
                    const float* __restrict__ bi,
                    const float* __restrict__ Wh,
                    const float* __restrict__ bhn,
                    float* __restrict__ out) {
    if (blockIdx.x == 0) bucketize(term);

    // input-side GEMM: gi = inputs @ Wi + bi
    do_gemm(inputs, Wi, g_gi, bi, T_STEPS, /*phase2=*/0, 0);
    grid_sync();

    const int maxL = __ldcg(&g_maxL);
    for (int s = 0; s <= maxL; s++) {
        int off = __ldcg(&g_off[s]);
        int cnt = __ldcg(&g_off[s + 1]) - off;
        if (s > 0) {
            do_gemm(out, Wh, g_gh, nullptr, cnt, /*phase2=*/1, off);
            grid_sync();
        }
        gates_pass(s, off, cnt, last_state, Wh, bhn, term, out);
        grid_sync();
    }
}

extern "C" void kernel_launch(void* const* d_in, const int* in_sizes, int n_in,
                              void* d_out, int out_size) {
    const float* inputs     = (const float*)d_in[0];
    const int*   term       = (const int*)d_in[1];
    const float* last_state = (const float*)d_in[2];
    const float* Wi         = (const float*)d_in[3];
    const float* bi         = (const float*)d_in[4];
    const float* Wh         = (const float*)d_in[5];
    const float* bhn        = (const float*)d_in[6];
    float*       out        = (float*)d_out;

    gru_persistent<<<GRID_BLOCKS, NT>>>(inputs, term, last_state,
                                        Wi, bi, Wh, bhn, out);
}